// round 1
// baseline (speedup 1.0000x reference)
#include <cuda_runtime.h>
#include <math.h>

// Problem constants
#define TSTEPS 128
#define BATCH  1024
#define INDIM  47
#define HID    646
#define OUTDIM 5

// GEMM tiling
#define MTILE 64
#define NTILE 64
#define KTILE 16
#define TPB   256

#define MT (BATCH / MTILE)                 // 16
#define NT ((HID + NTILE - 1) / NTILE)     // 11
#define TILES (MT * NT)                    // 176
#define SZ (BATCH * HID)                   // 661504

// Double-buffered recurrent state (device globals: no allocation allowed)
__device__ float g_h0[2][SZ];
__device__ float g_h1[2][SZ];

struct Job {
    const float* A1; int K1;   // first input segment  (x or h0)
    const float* A2; int K2;   // second input segment (recurrent h)
    const float* W1;           // [HID, K1] row-major
    const float* W2;           // [HID, K2] row-major
    const float* b1;
    const float* b2;
    float* C;                  // [BATCH, HID] output
};

__global__ void init_kernel() {
    int i = blockIdx.x * blockDim.x + threadIdx.x;
    if (i < SZ) {
        g_h0[1][i] = 0.0f;
        g_h1[1][i] = 0.0f;
    }
}

// Accumulate C_tile += A[m0:m0+64, :K] * W[n0:n0+64, :K]^T  (both K-contiguous, "NT" gemm)
// As/Bs are [KTILE][68] (stride 68 keeps float4 alignment and breaks bank conflicts
// on the transposed store: 4*68 = 272 ≡ 16 mod 32).
__device__ __forceinline__ void gemm_accum(
    const float* __restrict__ A, const float* __restrict__ W, int K,
    int m0, int n0, float acc[4][4],
    float* __restrict__ As, float* __restrict__ Bs, int tid)
{
    const int lrow = tid >> 2;          // 0..63 : tile row (m for A, n for W)
    const int lk4  = (tid & 3) << 2;    // 0,4,8,12 : k offset group
    const int tx   = tid & 15;          // micro-tile m group
    const int ty   = tid >> 4;          // micro-tile n group

    const float* Arow = A + (size_t)(m0 + lrow) * K;
    const bool wvalid = (n0 + lrow) < HID;
    const float* Wrow = W + (size_t)(n0 + lrow) * K;

    float ra[4], rb[4];
    // prefetch first k-tile into registers
    #pragma unroll
    for (int i = 0; i < 4; i++) {
        int k = lk4 + i;
        ra[i] = (k < K) ? Arow[k] : 0.0f;
        rb[i] = (k < K && wvalid) ? Wrow[k] : 0.0f;
    }

    for (int k0 = 0; k0 < K; k0 += KTILE) {
        #pragma unroll
        for (int i = 0; i < 4; i++) {
            As[(lk4 + i) * 68 + lrow] = ra[i];
            Bs[(lk4 + i) * 68 + lrow] = rb[i];
        }
        __syncthreads();

        // prefetch next k-tile (overlaps with FMA block below)
        int kn = k0 + KTILE;
        if (kn < K) {
            #pragma unroll
            for (int i = 0; i < 4; i++) {
                int k = kn + lk4 + i;
                ra[i] = (k < K) ? Arow[k] : 0.0f;
                rb[i] = (k < K && wvalid) ? Wrow[k] : 0.0f;
            }
        }

        #pragma unroll
        for (int kk = 0; kk < KTILE; kk++) {
            float4 a = *(const float4*)(As + kk * 68 + tx * 4);
            float4 b = *(const float4*)(Bs + kk * 68 + ty * 4);
            acc[0][0] += a.x * b.x; acc[0][1] += a.x * b.y; acc[0][2] += a.x * b.z; acc[0][3] += a.x * b.w;
            acc[1][0] += a.y * b.x; acc[1][1] += a.y * b.y; acc[1][2] += a.y * b.z; acc[1][3] += a.y * b.w;
            acc[2][0] += a.z * b.x; acc[2][1] += a.z * b.y; acc[2][2] += a.z * b.z; acc[2][3] += a.z * b.w;
            acc[3][0] += a.w * b.x; acc[3][1] += a.w * b.y; acc[3][2] += a.w * b.z; acc[3][3] += a.w * b.w;
        }
        __syncthreads();
    }
}

// One fused launch: job0 (tiles [0,176)) and job1 (tiles [176,352)).
// Each job computes C = tanh(A1 @ W1^T + b1 + A2 @ W2^T + b2).
__global__ __launch_bounds__(TPB) void cell_kernel(Job j0, Job j1) {
    __shared__ float As[KTILE * 68];
    __shared__ float Bs[KTILE * 68];

    const int bid = blockIdx.x;
    const Job jb = (bid < TILES) ? j0 : j1;
    const int tile = (bid < TILES) ? bid : (bid - TILES);
    const int m0 = (tile / NT) * MTILE;
    const int n0 = (tile % NT) * NTILE;
    const int tid = threadIdx.x;

    float acc[4][4] = {};
    gemm_accum(jb.A1, jb.W1, jb.K1, m0, n0, acc, As, Bs, tid);
    gemm_accum(jb.A2, jb.W2, jb.K2, m0, n0, acc, As, Bs, tid);

    const int tx = tid & 15, ty = tid >> 4;
    const int mb = m0 + tx * 4;
    const int nb = n0 + ty * 4;
    #pragma unroll
    for (int j = 0; j < 4; j++) {
        int n = nb + j;
        if (n < HID) {
            float bias = jb.b1[n] + jb.b2[n];
            #pragma unroll
            for (int i = 0; i < 4; i++) {
                jb.C[(size_t)(mb + i) * HID + n] = tanhf(acc[i][j] + bias);
            }
        }
    }
}

// logits[b,o] = h1[b,:] . Wout[o,:] + bout[o] ; one warp per (b,o)
__global__ void classifier_kernel(const float* __restrict__ h,
                                  const float* __restrict__ Wout,
                                  const float* __restrict__ bout,
                                  float* __restrict__ out) {
    int warp = (blockIdx.x * blockDim.x + threadIdx.x) >> 5;
    int lane = threadIdx.x & 31;
    if (warp >= BATCH * OUTDIM) return;
    int b = warp / OUTDIM, o = warp % OUTDIM;
    const float* hr = h + (size_t)b * HID;
    const float* wr = Wout + (size_t)o * HID;
    float s = 0.0f;
    for (int k = lane; k < HID; k += 32) s += hr[k] * wr[k];
    #pragma unroll
    for (int off = 16; off; off >>= 1) s += __shfl_down_sync(0xffffffff, s, off);
    if (lane == 0) out[b * OUTDIM + o] = s + bout[o];
}

extern "C" void kernel_launch(void* const* d_in, const int* in_sizes, int n_in,
                              void* d_out, int out_size) {
    const float* xs   = (const float*)d_in[0];
    const float* Wih0 = (const float*)d_in[1];
    const float* Whh0 = (const float*)d_in[2];
    const float* bih0 = (const float*)d_in[3];
    const float* bhh0 = (const float*)d_in[4];
    const float* Wih1 = (const float*)d_in[5];
    const float* Whh1 = (const float*)d_in[6];
    const float* bih1 = (const float*)d_in[7];
    const float* bhh1 = (const float*)d_in[8];
    const float* Wout = (const float*)d_in[9];
    const float* bout = (const float*)d_in[10];
    float* out = (float*)d_out;

    void* p;
    cudaGetSymbolAddress(&p, g_h0);
    float* h0b = (float*)p;              // h0b + parity*SZ
    cudaGetSymbolAddress(&p, g_h1);
    float* h1b = (float*)p;

    // zero the "t = -1" state slots (parity 1)
    init_kernel<<<(SZ + 255) / 256, 256>>>();

    // t = 0: layer0 only  h0(0) = f(x0, h0(-1)=0)
    {
        Job j0 = { xs, INDIM, h0b + SZ, HID, Wih0, Whh0, bih0, bhh0, h0b };
        cell_kernel<<<TILES, TPB>>>(j0, j0);
    }

    // t = 1..127: fused  h0(t) = f(x_t, h0(t-1))  ||  h1(t-1) = g(h0(t-1), h1(t-2))
    for (int t = 1; t < TSTEPS; t++) {
        const float* h0_prev = h0b + (size_t)((t - 1) & 1) * SZ;
        Job j0 = { xs + (size_t)t * BATCH * INDIM, INDIM,
                   h0_prev, HID,
                   Wih0, Whh0, bih0, bhh0,
                   h0b + (size_t)(t & 1) * SZ };
        Job j1 = { h0_prev, HID,
                   h1b + (size_t)(t & 1) * SZ,      // h1(t-2) lives at parity t%2
                   HID,
                   Wih1, Whh1, bih1, bhh1,
                   h1b + (size_t)((t - 1) & 1) * SZ };
        cell_kernel<<<2 * TILES, TPB>>>(j0, j1);
    }

    // drain: h1(127) = g(h0(127), h1(126))
    {
        Job jf = { h0b + SZ /* h0(127), parity 1 */, HID,
                   h1b /* h1(126), parity 0 */, HID,
                   Wih1, Whh1, bih1, bhh1,
                   h1b + SZ /* h1(127), parity 1 */ };
        cell_kernel<<<TILES, TPB>>>(jf, jf);
    }

    // classifier on h1(127)
    classifier_kernel<<<(BATCH * OUTDIM * 32 + 255) / 256, 256>>>(h1b + SZ, Wout, bout, out);
}